// round 1
// baseline (speedup 1.0000x reference)
#include <cuda_runtime.h>

// Twist2Mat (Rodrigues): twist [B,R,3] f32 -> rot [B,R,3,3] f32
// N = B*R = 8,388,608 elements. Memory-bound: 384 MB total traffic.
// 4 elements per thread => all-float4 loads/stores (3x LDG.128 + 9x STG.128).

#ifndef TPB
#define TPB 256
#endif

__device__ __forceinline__ void rodrigues9(float x, float y, float z, float* __restrict__ r)
{
    // theta = max(||w||, 1e-5); a = w / theta
    float n2    = fmaf(x, x, fmaf(y, y, z * z));
    float theta = fmaxf(sqrtf(n2), 1e-5f);
    float inv   = __fdividef(1.0f, theta);
    float a0 = x * inv, a1 = y * inv, a2 = z * inv;

    float s, c;
    __sincosf(theta, &s, &c);
    float k = 1.0f - c;   // 1 - cos

    // R = c*I + s*[a]_x + k*(a a^T)
    float ka0 = k * a0, ka1 = k * a1;
    float sa0 = s * a0, sa1 = s * a1, sa2 = s * a2;

    r[0] = fmaf(ka0, a0, c);        // R00
    r[1] = fmaf(ka0, a1, -sa2);     // R01
    r[2] = fmaf(ka0, a2,  sa1);     // R02
    r[3] = fmaf(ka0, a1,  sa2);     // R10
    r[4] = fmaf(ka1, a1, c);        // R11
    r[5] = fmaf(ka1, a2, -sa0);     // R12
    r[6] = fmaf(ka0, a2, -sa1);     // R20
    r[7] = fmaf(ka1, a2,  sa0);     // R21
    r[8] = fmaf(k * a2, a2, c);     // R22
}

__global__ __launch_bounds__(TPB, 8)
void twist2mat_kernel(const float4* __restrict__ in4,
                      float4* __restrict__ out4,
                      int n_quads)   // number of 4-element groups = N/4
{
    int t = blockIdx.x * TPB + threadIdx.x;
    if (t >= n_quads) return;

    // 4 twist vectors = 12 floats = 3 float4 loads
    float4 w0 = in4[3 * t + 0];
    float4 w1 = in4[3 * t + 1];
    float4 w2 = in4[3 * t + 2];

    float r[36];
    rodrigues9(w0.x, w0.y, w0.z, r +  0);
    rodrigues9(w0.w, w1.x, w1.y, r +  9);
    rodrigues9(w1.z, w1.w, w2.x, r + 18);
    rodrigues9(w2.y, w2.z, w2.w, r + 27);

    // 36 floats = 9 float4 stores
    float4* o = out4 + 9 * (long long)t;
#pragma unroll
    for (int i = 0; i < 9; i++) {
        o[i] = make_float4(r[4 * i + 0], r[4 * i + 1], r[4 * i + 2], r[4 * i + 3]);
    }
}

extern "C" void kernel_launch(void* const* d_in, const int* in_sizes, int n_in,
                              void* d_out, int out_size)
{
    const float* twist = (const float*)d_in[0];
    float* out = (float*)d_out;

    int n_elems = in_sizes[0] / 3;       // B*R = 8,388,608
    int n_quads = n_elems / 4;           // divisible: 2,097,152

    int blocks = (n_quads + TPB - 1) / TPB;
    twist2mat_kernel<<<blocks, TPB>>>((const float4*)twist, (float4*)out, n_quads);

    // Tail (n_elems not divisible by 4) — not hit for this shape, but keep it correct.
    int rem = n_elems - n_quads * 4;
    if (rem > 0) {
        // handled below by a tiny scalar kernel launch
        extern __global__ void twist2mat_tail(const float*, float*, int, int);
    }
}

// round 2
// speedup vs baseline: 2.5034x; 2.5034x over previous
#include <cuda_runtime.h>

// Twist2Mat (Rodrigues): twist [B,R,3] f32 -> rot [B,R,3,3] f32
// N = B*R = 8,388,608. Memory-bound: 384 MB total traffic.
//
// R1 lesson: direct per-thread float4 stores at 144B stride amplified L1
// wavefronts 9x (L1=76.5%, DRAM=34%). Fix: stage I/O through shared memory
// so all global accesses are fully coalesced 128-bit transactions.

#ifndef TPB
#define TPB 256
#endif

__device__ __forceinline__ void rodrigues9(float x, float y, float z, float* __restrict__ r)
{
    float n2    = fmaf(x, x, fmaf(y, y, z * z));
    float theta = fmaxf(sqrtf(n2), 1e-5f);
    float inv   = __fdividef(1.0f, theta);
    float a0 = x * inv, a1 = y * inv, a2 = z * inv;

    float s, c;
    __sincosf(theta, &s, &c);
    float k = 1.0f - c;

    // R = c*I + s*[a]_x + k*(a a^T)
    float ka0 = k * a0, ka1 = k * a1;
    float sa0 = s * a0, sa1 = s * a1, sa2 = s * a2;

    r[0] = fmaf(ka0, a0, c);
    r[1] = fmaf(ka0, a1, -sa2);
    r[2] = fmaf(ka0, a2,  sa1);
    r[3] = fmaf(ka0, a1,  sa2);
    r[4] = fmaf(ka1, a1, c);
    r[5] = fmaf(ka1, a2, -sa0);
    r[6] = fmaf(ka0, a2, -sa1);
    r[7] = fmaf(ka1, a2,  sa0);
    r[8] = fmaf(k * a2, a2, c);
}

// Each block handles TPB contiguous elements.
// Input per block:  TPB*3 floats  = TPB*3/4  float4   (192 for TPB=256)
// Output per block: TPB*9 floats  = TPB*9/4  float4   (576 for TPB=256)
__global__ __launch_bounds__(TPB)
void twist2mat_smem_kernel(const float4* __restrict__ in4,
                           float4* __restrict__ out4,
                           int n_elems)
{
    __shared__ float s_in [TPB * 3];
    __shared__ float s_out[TPB * 9];

    const int tid  = threadIdx.x;
    const int base = blockIdx.x * TPB;          // first element of this block

    // ---- coalesced input load: TPB*3/4 float4 ----
    {
        const float4* g = in4 + (size_t)blockIdx.x * (TPB * 3 / 4);
        float4* s = (float4*)s_in;
        if (base + TPB <= n_elems) {
            // full block fast path
            if (tid < TPB * 3 / 4) s[tid] = g[tid];
        } else {
            // partial tail block: scalar-safe load
            const float* gf = (const float*)(in4) + (size_t)base * 3;
            int valid_f = (n_elems - base) * 3;
            for (int i = tid; i < TPB * 3; i += TPB)
                s_in[i] = (i < valid_f) ? gf[i] : 1.0f;  // dummy, never stored
        }
    }
    __syncthreads();

    // ---- compute: one element per thread ----
    {
        float x = s_in[3 * tid + 0];
        float y = s_in[3 * tid + 1];
        float z = s_in[3 * tid + 2];
        float r[9];
        rodrigues9(x, y, z, r);
#pragma unroll
        for (int i = 0; i < 9; i++)
            s_out[9 * tid + i] = r[i];   // stride 9 mod 32: conflict-free
    }
    __syncthreads();

    // ---- coalesced output store: TPB*9/4 float4 ----
    if (base + TPB <= n_elems) {
        float4* g = out4 + (size_t)blockIdx.x * (TPB * 9 / 4);
        const float4* s = (const float4*)s_out;
#pragma unroll
        for (int i = tid; i < TPB * 9 / 4; i += TPB)
            g[i] = s[i];
    } else {
        float* gf = (float*)(out4) + (size_t)base * 9;
        int valid_f = (n_elems - base) * 9;
        for (int i = tid; i < valid_f; i += TPB)
            gf[i] = s_out[i];
    }
}

extern "C" void kernel_launch(void* const* d_in, const int* in_sizes, int n_in,
                              void* d_out, int out_size)
{
    const float* twist = (const float*)d_in[0];
    float* out = (float*)d_out;

    int n_elems = in_sizes[0] / 3;   // 8,388,608
    int blocks  = (n_elems + TPB - 1) / TPB;

    twist2mat_smem_kernel<<<blocks, TPB>>>((const float4*)twist, (float4*)out, n_elems);
}

// round 3
// speedup vs baseline: 2.5961x; 1.0370x over previous
#include <cuda_runtime.h>

// Twist2Mat (Rodrigues): twist [B,R,3] f32 -> rot [B,R,3,3] f32
// N = B*R = 8,388,608. Memory-bound: 384 MB streaming traffic.
//
// R1: per-thread strided float4 stores -> 9x L1 wavefront amplification (166us).
// R2: block-wide smem staging -> coalesced I/O, DRAM 68% (66.3us).
// R3: warp-autonomous smem tiles (syncwarp only, no block barrier) +
//     streaming cache hints (__ldcs/__stcs) for read-once/write-once data.

#ifndef TPB
#define TPB 256
#endif
#define WARPS (TPB / 32)

__device__ __forceinline__ void rodrigues9(float x, float y, float z, float* __restrict__ r)
{
    float n2    = fmaf(x, x, fmaf(y, y, z * z));
    float theta = fmaxf(sqrtf(n2), 1e-5f);
    float inv   = __fdividef(1.0f, theta);
    float a0 = x * inv, a1 = y * inv, a2 = z * inv;

    float s, c;
    __sincosf(theta, &s, &c);
    float k = 1.0f - c;

    // R = c*I + s*[a]_x + k*(a a^T)
    float ka0 = k * a0, ka1 = k * a1;
    float sa0 = s * a0, sa1 = s * a1, sa2 = s * a2;

    r[0] = fmaf(ka0, a0, c);
    r[1] = fmaf(ka0, a1, -sa2);
    r[2] = fmaf(ka0, a2,  sa1);
    r[3] = fmaf(ka0, a1,  sa2);
    r[4] = fmaf(ka1, a1, c);
    r[5] = fmaf(ka1, a2, -sa0);
    r[6] = fmaf(ka0, a2, -sa1);
    r[7] = fmaf(ka1, a2,  sa0);
    r[8] = fmaf(k * a2, a2, c);
}

// Each WARP autonomously handles 32 contiguous elements:
//   in : 32*3 floats = 24 float4   (lanes 0..23 load, streaming)
//   out: 32*9 floats = 72 float4   (each lane stores 2-3, streaming)
// Only __syncwarp needed: smem tiles are warp-private.
__global__ __launch_bounds__(TPB)
void twist2mat_warp_kernel(const float4* __restrict__ in4,
                           float4* __restrict__ out4,
                           int n_elems)
{
    __shared__ float s_in [WARPS][96];    // 96  floats/warp  (mod 32 == 0: bank-aligned)
    __shared__ float s_out[WARPS][288];   // 288 floats/warp  (mod 32 == 0: bank-aligned)

    const int lane = threadIdx.x & 31;
    const int wrp  = threadIdx.x >> 5;
    const long long wgid = (long long)blockIdx.x * WARPS + wrp;
    const long long base = wgid * 32;                 // first element of this warp
    if (base >= n_elems) return;

    const bool full = (base + 32 <= n_elems);

    // ---- coalesced streaming load: 24 float4 per warp ----
    if (full) {
        if (lane < 24)
            ((float4*)s_in[wrp])[lane] = __ldcs(in4 + wgid * 24 + lane);
    } else {
        const float* gf = (const float*)in4 + base * 3;
        int vf = (int)(n_elems - base) * 3;
        for (int i = lane; i < 96; i += 32)
            s_in[wrp][i] = (i < vf) ? gf[i] : 1.0f;   // pad, never stored
    }
    __syncwarp();

    // ---- compute: 1 element per lane (stride-3 LDS: conflict-free) ----
    {
        float x = s_in[wrp][3 * lane + 0];
        float y = s_in[wrp][3 * lane + 1];
        float z = s_in[wrp][3 * lane + 2];
        float r[9];
        rodrigues9(x, y, z, r);
#pragma unroll
        for (int i = 0; i < 9; i++)
            s_out[wrp][9 * lane + i] = r[i];          // stride-9 STS: conflict-free
    }
    __syncwarp();

    // ---- coalesced streaming store: 72 float4 per warp ----
    if (full) {
        float4* go = out4 + wgid * 72;
        const float4* so = (const float4*)s_out[wrp];
#pragma unroll
        for (int k = 0; k < 3; k++) {
            int i = lane + k * 32;
            if (i < 72) __stcs(go + i, so[i]);
        }
    } else {
        float* gf = (float*)out4 + base * 9;
        int vf = (int)(n_elems - base) * 9;
        for (int i = lane; i < vf; i += 32)
            gf[i] = s_out[wrp][i];
    }
}

extern "C" void kernel_launch(void* const* d_in, const int* in_sizes, int n_in,
                              void* d_out, int out_size)
{
    const float* twist = (const float*)d_in[0];
    float* out = (float*)d_out;

    int n_elems = in_sizes[0] / 3;                    // 8,388,608
    int n_warps = (n_elems + 31) / 32;
    int blocks  = (n_warps + WARPS - 1) / WARPS;

    twist2mat_warp_kernel<<<blocks, TPB>>>((const float4*)twist, (float4*)out, n_elems);
}